// round 1
// baseline (speedup 1.0000x reference)
#include <cuda_runtime.h>
#include <math.h>

// Problem dims
#define MROWS 16384   // B*T = 4*4096
#define DDIM  1024
#define TLEN  4096
#define BATCHN 4

// ---------------- scratch (device globals; no allocation allowed) ----------
__device__ float g_xn [MROWS * DDIM];
__device__ float g_lin[MROWS * DDIM];
__device__ float g_rg [MROWS * DDIM];
__device__ float g_rt [MROWS * DDIM];
__device__ float g_it [MROWS * DDIM];
__device__ float g_res[MROWS * DDIM];

// ---------------- packed f32x2 helpers (sm_100+) ---------------------------
__device__ __forceinline__ unsigned long long pk2(float x) {
    unsigned long long r;
    asm("mov.b64 %0, {%1, %1};" : "=l"(r) : "f"(x));
    return r;
}
__device__ __forceinline__ void fma2(unsigned long long& c,
                                     unsigned long long a,
                                     unsigned long long b) {
    asm("fma.rn.f32x2 %0, %1, %2, %3;" : "=l"(c) : "l"(a), "l"(b), "l"(c));
}
__device__ __forceinline__ float2 up2(unsigned long long v) {
    float2 f;
    asm("mov.b64 {%0, %1}, %2;" : "=f"(f.x), "=f"(f.y) : "l"(v));
    return f;
}

// ---------------- math helpers ---------------------------------------------
__device__ __forceinline__ float gelu_exact(float x) {
    return 0.5f * x * (1.0f + erff(x * 0.70710678118654752440f));
}
__device__ __forceinline__ float sigmoidf_(float x) {
    return 1.0f / (1.0f + expf(-x));
}

// ---------------- rmsnorm (F.normalize * sqrt(D) * g) ----------------------
// one block (256 thr) per row; each thread handles one float4 (1024 = 256*4)
__global__ void rmsnorm_kernel(const float* __restrict__ x,
                               const float* __restrict__ gw,
                               float* __restrict__ y) {
    int row = blockIdx.x;
    const float4* xr = (const float4*)(x + (size_t)row * DDIM);
    float4 v = xr[threadIdx.x];
    float ss = v.x * v.x + v.y * v.y + v.z * v.z + v.w * v.w;
    #pragma unroll
    for (int o = 16; o > 0; o >>= 1) ss += __shfl_xor_sync(0xffffffffu, ss, o);
    __shared__ float sred[8];
    if ((threadIdx.x & 31) == 0) sred[threadIdx.x >> 5] = ss;
    __syncthreads();
    float total = 0.0f;
    #pragma unroll
    for (int i = 0; i < 8; i++) total += sred[i];
    float n = fmaxf(sqrtf(total), 1e-12f);
    float s = 32.0f / n;  // sqrt(1024) = 32
    float4 g = ((const float4*)gw)[threadIdx.x];
    float4 o;
    o.x = v.x * s * g.x; o.y = v.y * s * g.y;
    o.z = v.z * s * g.z; o.w = v.w * s * g.w;
    ((float4*)(y + (size_t)row * DDIM))[threadIdx.x] = o;
}

// ---------------- SGEMM: C[M,N] = A[M,K] @ W[N,K]^T + bias (+ add) ---------
// BM=BN=128, BK=8, 256 threads, 8x8 per thread, inner loop in fma.rn.f32x2
__global__ void __launch_bounds__(256, 2)
gemm_kernel(const float* __restrict__ A, const float* __restrict__ W,
            const float* __restrict__ bias, const float* __restrict__ addp,
            float* __restrict__ C, int M, int N, int K, int doAdd) {
    __shared__ float As[8][128];
    __shared__ float Bs[8][128];

    int tid = threadIdx.x;
    int tx = tid & 15, ty = tid >> 4;
    int m0 = ty * 8, n0 = tx * 8;
    int ar = tid >> 1, ac = (tid & 1) * 4;

    const float* Aptr = A + (size_t)(blockIdx.y * 128 + ar) * K + ac;
    const float* Wptr = W + (size_t)(blockIdx.x * 128 + ar) * K + ac;

    unsigned long long acc[8][4];
    #pragma unroll
    for (int i = 0; i < 8; i++)
        #pragma unroll
        for (int j = 0; j < 4; j++) acc[i][j] = 0ull;

    float4 av = *(const float4*)Aptr;
    float4 bv = *(const float4*)Wptr;

    int nk = K >> 3;
    for (int kt = 0; kt < nk; kt++) {
        As[ac + 0][ar] = av.x; As[ac + 1][ar] = av.y;
        As[ac + 2][ar] = av.z; As[ac + 3][ar] = av.w;
        Bs[ac + 0][ar] = bv.x; Bs[ac + 1][ar] = bv.y;
        Bs[ac + 2][ar] = bv.z; Bs[ac + 3][ar] = bv.w;
        __syncthreads();

        if (kt + 1 < nk) {
            Aptr += 8; Wptr += 8;
            av = *(const float4*)Aptr;
            bv = *(const float4*)Wptr;
        }

        #pragma unroll
        for (int k = 0; k < 8; k++) {
            float4 aA = *(const float4*)&As[k][m0];
            float4 aB = *(const float4*)&As[k][m0 + 4];
            ulonglong2 b01 = *(const ulonglong2*)&Bs[k][n0];
            ulonglong2 b23 = *(const ulonglong2*)&Bs[k][n0 + 4];
            unsigned long long a2[8];
            a2[0] = pk2(aA.x); a2[1] = pk2(aA.y); a2[2] = pk2(aA.z); a2[3] = pk2(aA.w);
            a2[4] = pk2(aB.x); a2[5] = pk2(aB.y); a2[6] = pk2(aB.z); a2[7] = pk2(aB.w);
            #pragma unroll
            for (int i = 0; i < 8; i++) {
                fma2(acc[i][0], a2[i], b01.x);
                fma2(acc[i][1], a2[i], b01.y);
                fma2(acc[i][2], a2[i], b23.x);
                fma2(acc[i][3], a2[i], b23.y);
            }
        }
        __syncthreads();
    }

    int gm = blockIdx.y * 128 + m0;
    int gn = blockIdx.x * 128 + n0;
    float4 bias0 = *(const float4*)&bias[gn];
    float4 bias1 = *(const float4*)&bias[gn + 4];
    #pragma unroll
    for (int i = 0; i < 8; i++) {
        float2 c0 = up2(acc[i][0]); float2 c1 = up2(acc[i][1]);
        float2 c2 = up2(acc[i][2]); float2 c3 = up2(acc[i][3]);
        float4 o0 = make_float4(c0.x + bias0.x, c0.y + bias0.y,
                                c1.x + bias0.z, c1.y + bias0.w);
        float4 o1 = make_float4(c2.x + bias1.x, c2.y + bias1.y,
                                c3.x + bias1.z, c3.y + bias1.w);
        size_t off = (size_t)(gm + i) * N + gn;
        if (doAdd) {
            float4 r0 = *(const float4*)(addp + off);
            float4 r1 = *(const float4*)(addp + off + 4);
            o0.x += r0.x; o0.y += r0.y; o0.z += r0.z; o0.w += r0.w;
            o1.x += r1.x; o1.y += r1.y; o1.z += r1.z; o1.w += r1.w;
        }
        *(float4*)(C + off)     = o0;
        *(float4*)(C + off + 4) = o1;
    }
}

// ---------------- RG-LRU gate prep (elementwise) ---------------------------
// in: rt_pre, it_pre, rg(x).  out: rt <- a, it <- gated
__global__ void gateprep_kernel(float* __restrict__ rt, float* __restrict__ it,
                                const float* __restrict__ rg,
                                const float* __restrict__ Lam) {
    int i = blockIdx.x * blockDim.x + threadIdx.x;
    if (i >= MROWS * DDIM / 4) return;
    float4 r  = ((const float4*)rt)[i];
    float4 iv = ((const float4*)it)[i];
    float4 xv = ((const float4*)rg)[i];
    float4 lam = ((const float4*)Lam)[i & (DDIM / 4 - 1)];

    float4 ao, go;
    {
        float la = -log1pf(expf(-lam.x));
        float a = expf(la * sigmoidf_(r.x) * 0.125f);
        ao.x = a; go.x = sqrtf(fmaxf(1.0f - a * a, 0.0f)) * sigmoidf_(iv.x) * xv.x;
    }
    {
        float la = -log1pf(expf(-lam.y));
        float a = expf(la * sigmoidf_(r.y) * 0.125f);
        ao.y = a; go.y = sqrtf(fmaxf(1.0f - a * a, 0.0f)) * sigmoidf_(iv.y) * xv.y;
    }
    {
        float la = -log1pf(expf(-lam.z));
        float a = expf(la * sigmoidf_(r.z) * 0.125f);
        ao.z = a; go.z = sqrtf(fmaxf(1.0f - a * a, 0.0f)) * sigmoidf_(iv.z) * xv.z;
    }
    {
        float la = -log1pf(expf(-lam.w));
        float a = expf(la * sigmoidf_(r.w) * 0.125f);
        ao.w = a; go.w = sqrtf(fmaxf(1.0f - a * a, 0.0f)) * sigmoidf_(iv.w) * xv.w;
    }
    ((float4*)rt)[i] = ao;
    ((float4*)it)[i] = go;
}

// ---------------- sequential linear recurrence h = a*h + g -----------------
// 4096 independent chains (one per (b,d)); one thread per chain, prefetch 8
__global__ void scan_kernel(const float* __restrict__ Av,
                            const float* __restrict__ Gv,
                            float* __restrict__ H) {
    int t = blockIdx.x * 32 + threadIdx.x;      // 0..4095
    int b = t >> 10, d = t & (DDIM - 1);
    size_t base = ((size_t)b * TLEN) * DDIM + d;
    const float* pa = Av + base;
    const float* pg = Gv + base;
    float* ph = H + base;

    const int UN = 8;
    float a0[UN], g0[UN], a1[UN], g1[UN];
    float h = 0.0f;
    #pragma unroll
    for (int j = 0; j < UN; j++) { a0[j] = pa[j * DDIM]; g0[j] = pg[j * DDIM]; }
    pa += UN * DDIM; pg += UN * DDIM;

    for (int c = 0; c < TLEN / UN; c++) {
        if (c + 1 < TLEN / UN) {
            #pragma unroll
            for (int j = 0; j < UN; j++) { a1[j] = pa[j * DDIM]; g1[j] = pg[j * DDIM]; }
            pa += UN * DDIM; pg += UN * DDIM;
        }
        #pragma unroll
        for (int j = 0; j < UN; j++) {
            h = fmaf(a0[j], h, g0[j]);
            ph[j * DDIM] = h;
        }
        ph += UN * DDIM;
        #pragma unroll
        for (int j = 0; j < UN; j++) { a0[j] = a1[j]; g0[j] = g1[j]; }
    }
}

// ---------------- lin <- gelu(lin) * h  ------------------------------------
__global__ void mult_kernel(float* __restrict__ lin, const float* __restrict__ h) {
    int i = blockIdx.x * blockDim.x + threadIdx.x;
    if (i >= MROWS * DDIM / 4) return;
    float4 l = ((const float4*)lin)[i];
    float4 hv = ((const float4*)h)[i];
    l.x = gelu_exact(l.x) * hv.x;
    l.y = gelu_exact(l.y) * hv.y;
    l.z = gelu_exact(l.z) * hv.z;
    l.w = gelu_exact(l.w) * hv.w;
    ((float4*)lin)[i] = l;
}

// ---------------- lin <- gelu(sigmoid(t1)) * t2  ---------------------------
__global__ void comb_kernel(float* __restrict__ lin,
                            const float* __restrict__ t1,
                            const float* __restrict__ t2) {
    int i = blockIdx.x * blockDim.x + threadIdx.x;
    if (i >= MROWS * DDIM / 4) return;
    float4 a = ((const float4*)t1)[i];
    float4 b = ((const float4*)t2)[i];
    float4 o;
    o.x = gelu_exact(sigmoidf_(a.x)) * b.x;
    o.y = gelu_exact(sigmoidf_(a.y)) * b.y;
    o.z = gelu_exact(sigmoidf_(a.z)) * b.z;
    o.w = gelu_exact(sigmoidf_(a.w)) * b.w;
    ((float4*)lin)[i] = o;
}

// ---------------- launch ---------------------------------------------------
extern "C" void kernel_launch(void* const* d_in, const int* in_sizes, int n_in,
                              void* d_out, int out_size) {
    const float* x      = (const float*)d_in[0];
    const float* g1     = (const float*)d_in[1];
    const float* g2     = (const float*)d_in[2];
    const float* W_lin  = (const float*)d_in[3];
    const float* b_lin  = (const float*)d_in[4];
    const float* W_conv = (const float*)d_in[5];
    const float* b_conv = (const float*)d_in[6];
    const float* W_lin2 = (const float*)d_in[7];
    const float* b_lin2 = (const float*)d_in[8];
    const float* Wa     = (const float*)d_in[9];
    const float* ba     = (const float*)d_in[10];
    const float* Wx     = (const float*)d_in[11];
    const float* bx     = (const float*)d_in[12];
    const float* Lam    = (const float*)d_in[13];
    const float* W1     = (const float*)d_in[14];
    const float* b1     = (const float*)d_in[15];
    const float* W2     = (const float*)d_in[16];
    const float* b2     = (const float*)d_in[17];
    const float* W3     = (const float*)d_in[18];
    const float* b3     = (const float*)d_in[19];
    float* out = (float*)d_out;

    float *xn, *lin, *rg, *rt, *it, *res;
    cudaGetSymbolAddress((void**)&xn,  g_xn);
    cudaGetSymbolAddress((void**)&lin, g_lin);
    cudaGetSymbolAddress((void**)&rg,  g_rg);
    cudaGetSymbolAddress((void**)&rt,  g_rt);
    cudaGetSymbolAddress((void**)&it,  g_it);
    cudaGetSymbolAddress((void**)&res, g_res);

    dim3 gg(DDIM / 128, MROWS / 128);   // (8, 128)
    dim3 gb(256);
    int ewBlocks = (MROWS * DDIM / 4 + 255) / 256;

    // 1) xn = rmsnorm(x, g1)
    rmsnorm_kernel<<<MROWS, 256>>>(x, g1, xn);
    // 2) lin = xn @ W_lin^T + b_lin
    gemm_kernel<<<gg, gb>>>(xn, W_lin, b_lin, nullptr, lin, MROWS, DDIM, DDIM, 0);
    // 3) rg = lin @ W_conv^T + b_conv
    gemm_kernel<<<gg, gb>>>(lin, W_conv, b_conv, nullptr, rg, MROWS, DDIM, DDIM, 0);
    // 4) rt = rg @ Wa^T + ba ; it = rg @ Wx^T + bx
    gemm_kernel<<<gg, gb>>>(rg, Wa, ba, nullptr, rt, MROWS, DDIM, DDIM, 0);
    gemm_kernel<<<gg, gb>>>(rg, Wx, bx, nullptr, it, MROWS, DDIM, DDIM, 0);
    // 5) rt <- a, it <- gated
    gateprep_kernel<<<ewBlocks, 256>>>(rt, it, rg, Lam);
    // 6) rg <- scan(a, gated)
    scan_kernel<<<128, 32>>>(rt, it, rg);
    // 7) lin <- gelu(lin) * rg
    mult_kernel<<<ewBlocks, 256>>>(lin, rg);
    // 8) res = lin @ W_lin2^T + b_lin2 + x
    gemm_kernel<<<gg, gb>>>(lin, W_lin2, b_lin2, x, res, MROWS, DDIM, DDIM, 1);
    // 9) xn = rmsnorm(res, g2)
    rmsnorm_kernel<<<MROWS, 256>>>(res, g2, xn);
    // 10) rt = xn @ W1^T + b1 ; it = xn @ W2^T + b2
    gemm_kernel<<<gg, gb>>>(xn, W1, b1, nullptr, rt, MROWS, DDIM, DDIM, 0);
    gemm_kernel<<<gg, gb>>>(xn, W2, b2, nullptr, it, MROWS, DDIM, DDIM, 0);
    // 11) lin <- gelu(sigmoid(rt)) * it
    comb_kernel<<<ewBlocks, 256>>>(lin, rt, it);
    // 12) out = lin @ W3^T + b3 + res
    gemm_kernel<<<gg, gb>>>(lin, W3, b3, res, out, MROWS, DDIM, DDIM, 1);

    (void)in_sizes; (void)n_in; (void)out_size;
}

// round 3
// speedup vs baseline: 2.6919x; 2.6919x over previous
#include <cuda_runtime.h>
#include <cuda_bf16.h>
#include <math.h>
#include <cstdint>

// Problem dims
#define MROWS 16384   // B*T = 4*4096
#define DDIM  1024
#define TLEN  4096

// ---------------- scratch (device globals; no allocation allowed) ----------
__device__ float g_xn [MROWS * DDIM];
__device__ float g_lin[MROWS * DDIM];
__device__ float g_rg [MROWS * DDIM];
__device__ float g_rt [MROWS * DDIM];
__device__ float g_it [MROWS * DDIM];
__device__ float g_res[MROWS * DDIM];
__device__ __nv_bfloat16 g_Ah[MROWS * DDIM];
__device__ __nv_bfloat16 g_Al[MROWS * DDIM];
__device__ __nv_bfloat16 g_Wh[DDIM * DDIM];
__device__ __nv_bfloat16 g_Wl[DDIM * DDIM];

// ---------------- base-ISA tensor helpers (sm_80+ ; no tcgen05) ------------
__device__ __forceinline__ uint32_t smem_to_u32(const void* p) {
    uint32_t a;
    asm("{ .reg .u64 t; cvta.to.shared.u64 t, %1; cvt.u32.u64 %0, t; }"
        : "=r"(a) : "l"(p));
    return a;
}
__device__ __forceinline__ void cpasync16(uint32_t dst, const void* src) {
    asm volatile("cp.async.cg.shared.global [%0], [%1], 16;"
                 :: "r"(dst), "l"(src) : "memory");
}
#define CP_COMMIT() asm volatile("cp.async.commit_group;" ::: "memory")
#define CP_WAIT(n)  asm volatile("cp.async.wait_group %0;" :: "n"(n) : "memory")

__device__ __forceinline__ void ldsm4(uint32_t addr, uint32_t* r) {
    asm volatile("ldmatrix.sync.aligned.m8n8.x4.shared.b16 {%0,%1,%2,%3}, [%4];"
                 : "=r"(r[0]), "=r"(r[1]), "=r"(r[2]), "=r"(r[3]) : "r"(addr));
}
__device__ __forceinline__ void mma16816(float* c, const uint32_t* a, const uint32_t* b) {
    asm volatile(
        "mma.sync.aligned.m16n8k16.row.col.f32.bf16.bf16.f32 "
        "{%0,%1,%2,%3}, {%4,%5,%6,%7}, {%8,%9}, {%0,%1,%2,%3};"
        : "+f"(c[0]), "+f"(c[1]), "+f"(c[2]), "+f"(c[3])
        : "r"(a[0]), "r"(a[1]), "r"(a[2]), "r"(a[3]), "r"(b[0]), "r"(b[1]));
}

// ---------------- math helpers ---------------------------------------------
__device__ __forceinline__ float gelu_exact(float x) {
    return 0.5f * x * (1.0f + erff(x * 0.70710678118654752440f));
}
__device__ __forceinline__ float sigmoidf_(float x) {
    return 1.0f / (1.0f + expf(-x));
}

// ---------------- fp32 -> (hi, lo) bf16 split ------------------------------
__global__ void split_kernel(const float* __restrict__ src,
                             __nv_bfloat16* __restrict__ hi,
                             __nv_bfloat16* __restrict__ lo, int n4) {
    int i = blockIdx.x * 256 + threadIdx.x;
    if (i >= n4) return;
    float4 v = ((const float4*)src)[i];
    __nv_bfloat162 h01 = __floats2bfloat162_rn(v.x, v.y);
    __nv_bfloat162 h23 = __floats2bfloat162_rn(v.z, v.w);
    float r0 = v.x - __low2float(h01);
    float r1 = v.y - __high2float(h01);
    float r2 = v.z - __low2float(h23);
    float r3 = v.w - __high2float(h23);
    __nv_bfloat162 l01 = __floats2bfloat162_rn(r0, r1);
    __nv_bfloat162 l23 = __floats2bfloat162_rn(r2, r3);
    ((__nv_bfloat162*)hi)[2 * i]     = h01;
    ((__nv_bfloat162*)hi)[2 * i + 1] = h23;
    ((__nv_bfloat162*)lo)[2 * i]     = l01;
    ((__nv_bfloat162*)lo)[2 * i + 1] = l23;
}

// ---------------- split-bf16 mma.sync GEMM ---------------------------------
// C[M,N] = (Ah+Al)[M,K] @ (Bh+Bl)[N,K]^T + bias (+ add), fp32 accumulate.
// CTA tile 128x128, K-chunk 64, 3-stage cp.async pipeline, 256 threads.
#define TILE_BYTES  16384            // 128 x 64 bf16
#define STAGE_BYTES 65536            // 4 tiles: Ah, Al, Bh, Bl
#define NSTAGE 3
#define NCHUNK (DDIM / 64)           // 16

__device__ __forceinline__ uint32_t swaddr(uint32_t tile, uint32_t row, uint32_t kb) {
    uint32_t off = row * 128u + kb;
    return tile + (off ^ ((off >> 3) & 0x70u));
}

__global__ void __launch_bounds__(256, 1)
mma_gemm_kernel(const __nv_bfloat16* __restrict__ Ah, const __nv_bfloat16* __restrict__ Al,
                const __nv_bfloat16* __restrict__ Bh, const __nv_bfloat16* __restrict__ Bl,
                const float* __restrict__ bias, const float* __restrict__ addp,
                float* __restrict__ C, int doAdd) {
    extern __shared__ __align__(1024) char smem_raw[];
    uint32_t smem0 = smem_to_u32(smem_raw);
    uint32_t tbase = (smem0 + 1023u) & ~1023u;

    int tid = threadIdx.x;
    int wid = tid >> 5;
    int lane = tid & 31;
    int m0 = blockIdx.y * 128;
    int n0 = blockIdx.x * 128;

    // ---- producer mapping: 4 tiles * 128 rows * 8 x 16B; 16 vecs/thread ----
    int row_base = tid >> 3;        // 0..31
    int col = tid & 7;              // 16B-chunk within 128B row
    const char* srcb[16];
    uint32_t stsoff[16];
    {
        const char* base4[4];
        base4[0] = (const char*)(Ah + (size_t)m0 * DDIM);
        base4[1] = (const char*)(Al + (size_t)m0 * DDIM);
        base4[2] = (const char*)(Bh + (size_t)n0 * DDIM);
        base4[3] = (const char*)(Bl + (size_t)n0 * DDIM);
        #pragma unroll
        for (int i = 0; i < 16; i++) {
            uint32_t rr = (uint32_t)row_base + 32u * (i & 3);
            srcb[i] = base4[i >> 2] + (size_t)rr * 2048 + col * 16;
            uint32_t off = rr * 128u + (uint32_t)col * 16u;
            stsoff[i] = (uint32_t)(i >> 2) * TILE_BYTES + (off ^ ((off >> 3) & 0x70u));
        }
    }

    #define ISSUE_STAGE(buf, chunk) do { \
        uint32_t db_ = tbase + (uint32_t)(buf) * STAGE_BYTES; \
        _Pragma("unroll") \
        for (int i_ = 0; i_ < 16; i_++) \
            cpasync16(db_ + stsoff[i_], srcb[i_] + (size_t)(chunk) * 128); \
        CP_COMMIT(); \
    } while (0)

    // ---- consumer mapping ----
    int warp_m = wid & 3;           // 4 warps along M (32 rows each)
    int warp_n = wid >> 2;          // 2 warps along N (64 cols each)
    // lane address components for ldmatrix
    uint32_t ar  = (uint32_t)((lane & 7) + ((lane >> 3) & 1) * 8);
    uint32_t akb = (uint32_t)(((lane >> 4) & 1) * 16);
    uint32_t br  = (uint32_t)((lane & 7) + ((lane >> 4) & 1) * 8);
    uint32_t bkb = (uint32_t)(((lane >> 3) & 1) * 16);

    float acc[2][8][4];
    #pragma unroll
    for (int i = 0; i < 2; i++)
        #pragma unroll
        for (int j = 0; j < 8; j++)
            #pragma unroll
            for (int q = 0; q < 4; q++) acc[i][j][q] = 0.0f;

    ISSUE_STAGE(0, 0);
    ISSUE_STAGE(1, 1);

    for (int c = 0; c < NCHUNK; c++) {
        if (c + 2 >= NCHUNK) { CP_WAIT(0); } else { CP_WAIT(1); }
        __syncthreads();
        uint32_t sb = tbase + (uint32_t)(c % NSTAGE) * STAGE_BYTES;
        uint32_t tAh = sb;
        uint32_t tAl = sb + TILE_BYTES;
        uint32_t tBh = sb + 2 * TILE_BYTES;
        uint32_t tBl = sb + 3 * TILE_BYTES;

        #pragma unroll
        for (int k16 = 0; k16 < 4; k16++) {
            uint32_t kb = (uint32_t)k16 * 32u;
            uint32_t ah[2][4], al[2][4], bh[4][4], bl[4][4];
            #pragma unroll
            for (int mt = 0; mt < 2; mt++)
                ldsm4(swaddr(tAh, (uint32_t)(warp_m * 32 + mt * 16) + ar, kb + akb), ah[mt]);
            #pragma unroll
            for (int p = 0; p < 4; p++)
                ldsm4(swaddr(tBh, (uint32_t)(warp_n * 64 + p * 16) + br, kb + bkb), bh[p]);
            // term 1: Ah @ Bh
            #pragma unroll
            for (int mt = 0; mt < 2; mt++)
                #pragma unroll
                for (int p = 0; p < 4; p++) {
                    mma16816(acc[mt][2 * p],     ah[mt], &bh[p][0]);
                    mma16816(acc[mt][2 * p + 1], ah[mt], &bh[p][2]);
                }
            // term 2: Ah @ Bl
            #pragma unroll
            for (int p = 0; p < 4; p++)
                ldsm4(swaddr(tBl, (uint32_t)(warp_n * 64 + p * 16) + br, kb + bkb), bl[p]);
            #pragma unroll
            for (int mt = 0; mt < 2; mt++)
                #pragma unroll
                for (int p = 0; p < 4; p++) {
                    mma16816(acc[mt][2 * p],     ah[mt], &bl[p][0]);
                    mma16816(acc[mt][2 * p + 1], ah[mt], &bl[p][2]);
                }
            // term 3: Al @ Bh
            #pragma unroll
            for (int mt = 0; mt < 2; mt++)
                ldsm4(swaddr(tAl, (uint32_t)(warp_m * 32 + mt * 16) + ar, kb + akb), al[mt]);
            #pragma unroll
            for (int mt = 0; mt < 2; mt++)
                #pragma unroll
                for (int p = 0; p < 4; p++) {
                    mma16816(acc[mt][2 * p],     al[mt], &bh[p][0]);
                    mma16816(acc[mt][2 * p + 1], al[mt], &bh[p][2]);
                }
        }
        __syncthreads();
        if (c + 2 < NCHUNK) ISSUE_STAGE((c + 2) % NSTAGE, c + 2);
    }

    // ---- epilogue ----
    int lm = lane >> 2;
    int lc = (lane & 3) * 2;
    int cm = m0 + warp_m * 32;
    int cn = n0 + warp_n * 64;
    #pragma unroll
    for (int mt = 0; mt < 2; mt++) {
        #pragma unroll
        for (int nt = 0; nt < 8; nt++) {
            int r0 = cm + mt * 16 + lm;
            int cc = cn + nt * 8 + lc;
            float2 bv = *(const float2*)&bias[cc];
            float* a = acc[mt][nt];
            float2 o0 = make_float2(a[0] + bv.x, a[1] + bv.y);
            float2 o1 = make_float2(a[2] + bv.x, a[3] + bv.y);
            size_t off0 = (size_t)r0 * DDIM + cc;
            size_t off1 = (size_t)(r0 + 8) * DDIM + cc;
            if (doAdd) {
                float2 q0 = *(const float2*)(addp + off0);
                float2 q1 = *(const float2*)(addp + off1);
                o0.x += q0.x; o0.y += q0.y;
                o1.x += q1.x; o1.y += q1.y;
            }
            *(float2*)(C + off0) = o0;
            *(float2*)(C + off1) = o1;
        }
    }
}

// ---------------- rmsnorm (F.normalize * sqrt(D) * g) ----------------------
__global__ void rmsnorm_kernel(const float* __restrict__ x,
                               const float* __restrict__ gw,
                               float* __restrict__ y) {
    int row = blockIdx.x;
    const float4* xr = (const float4*)(x + (size_t)row * DDIM);
    float4 v = xr[threadIdx.x];
    float ss = v.x * v.x + v.y * v.y + v.z * v.z + v.w * v.w;
    #pragma unroll
    for (int o = 16; o > 0; o >>= 1) ss += __shfl_xor_sync(0xffffffffu, ss, o);
    __shared__ float sred[8];
    if ((threadIdx.x & 31) == 0) sred[threadIdx.x >> 5] = ss;
    __syncthreads();
    float total = 0.0f;
    #pragma unroll
    for (int i = 0; i < 8; i++) total += sred[i];
    float n = fmaxf(sqrtf(total), 1e-12f);
    float s = 32.0f / n;
    float4 g = ((const float4*)gw)[threadIdx.x];
    float4 o;
    o.x = v.x * s * g.x; o.y = v.y * s * g.y;
    o.z = v.z * s * g.z; o.w = v.w * s * g.w;
    ((float4*)(y + (size_t)row * DDIM))[threadIdx.x] = o;
}

// ---------------- RG-LRU gate prep -----------------------------------------
__global__ void gateprep_kernel(float* __restrict__ rt, float* __restrict__ it,
                                const float* __restrict__ rg,
                                const float* __restrict__ Lam) {
    int i = blockIdx.x * blockDim.x + threadIdx.x;
    if (i >= MROWS * DDIM / 4) return;
    float4 r  = ((const float4*)rt)[i];
    float4 iv = ((const float4*)it)[i];
    float4 xv = ((const float4*)rg)[i];
    float4 lam = ((const float4*)Lam)[i & (DDIM / 4 - 1)];
    float4 ao, go;
    {
        float la = -log1pf(expf(-lam.x));
        float a = expf(la * sigmoidf_(r.x) * 0.125f);
        ao.x = a; go.x = sqrtf(fmaxf(1.0f - a * a, 0.0f)) * sigmoidf_(iv.x) * xv.x;
    }
    {
        float la = -log1pf(expf(-lam.y));
        float a = expf(la * sigmoidf_(r.y) * 0.125f);
        ao.y = a; go.y = sqrtf(fmaxf(1.0f - a * a, 0.0f)) * sigmoidf_(iv.y) * xv.y;
    }
    {
        float la = -log1pf(expf(-lam.z));
        float a = expf(la * sigmoidf_(r.z) * 0.125f);
        ao.z = a; go.z = sqrtf(fmaxf(1.0f - a * a, 0.0f)) * sigmoidf_(iv.z) * xv.z;
    }
    {
        float la = -log1pf(expf(-lam.w));
        float a = expf(la * sigmoidf_(r.w) * 0.125f);
        ao.w = a; go.w = sqrtf(fmaxf(1.0f - a * a, 0.0f)) * sigmoidf_(iv.w) * xv.w;
    }
    ((float4*)rt)[i] = ao;
    ((float4*)it)[i] = go;
}

// ---------------- sequential linear recurrence h = a*h + g -----------------
__global__ void scan_kernel(const float* __restrict__ Av,
                            const float* __restrict__ Gv,
                            float* __restrict__ H) {
    int t = blockIdx.x * 32 + threadIdx.x;      // 0..4095
    int b = t >> 10, d = t & (DDIM - 1);
    size_t base = ((size_t)b * TLEN) * DDIM + d;
    const float* pa = Av + base;
    const float* pg = Gv + base;
    float* ph = H + base;

    const int UN = 8;
    float a0[UN], g0[UN], a1[UN], g1[UN];
    float h = 0.0f;
    #pragma unroll
    for (int j = 0; j < UN; j++) { a0[j] = pa[j * DDIM]; g0[j] = pg[j * DDIM]; }
    pa += UN * DDIM; pg += UN * DDIM;

    for (int c = 0; c < TLEN / UN; c++) {
        if (c + 1 < TLEN / UN) {
            #pragma unroll
            for (int j = 0; j < UN; j++) { a1[j] = pa[j * DDIM]; g1[j] = pg[j * DDIM]; }
            pa += UN * DDIM; pg += UN * DDIM;
        }
        #pragma unroll
        for (int j = 0; j < UN; j++) {
            h = fmaf(a0[j], h, g0[j]);
            ph[j * DDIM] = h;
        }
        ph += UN * DDIM;
        #pragma unroll
        for (int j = 0; j < UN; j++) { a0[j] = a1[j]; g0[j] = g1[j]; }
    }
}

// ---------------- lin <- gelu(lin) * h  ------------------------------------
__global__ void mult_kernel(float* __restrict__ lin, const float* __restrict__ h) {
    int i = blockIdx.x * blockDim.x + threadIdx.x;
    if (i >= MROWS * DDIM / 4) return;
    float4 l = ((const float4*)lin)[i];
    float4 hv = ((const float4*)h)[i];
    l.x = gelu_exact(l.x) * hv.x;
    l.y = gelu_exact(l.y) * hv.y;
    l.z = gelu_exact(l.z) * hv.z;
    l.w = gelu_exact(l.w) * hv.w;
    ((float4*)lin)[i] = l;
}

// ---------------- lin <- gelu(sigmoid(t1)) * t2  ---------------------------
__global__ void comb_kernel(float* __restrict__ lin,
                            const float* __restrict__ t1,
                            const float* __restrict__ t2) {
    int i = blockIdx.x * blockDim.x + threadIdx.x;
    if (i >= MROWS * DDIM / 4) return;
    float4 a = ((const float4*)t1)[i];
    float4 b = ((const float4*)t2)[i];
    float4 o;
    o.x = gelu_exact(sigmoidf_(a.x)) * b.x;
    o.y = gelu_exact(sigmoidf_(a.y)) * b.y;
    o.z = gelu_exact(sigmoidf_(a.z)) * b.z;
    o.w = gelu_exact(sigmoidf_(a.w)) * b.w;
    ((float4*)lin)[i] = o;
}

// ---------------- launch ---------------------------------------------------
extern "C" void kernel_launch(void* const* d_in, const int* in_sizes, int n_in,
                              void* d_out, int out_size) {
    const float* x      = (const float*)d_in[0];
    const float* g1     = (const float*)d_in[1];
    const float* g2     = (const float*)d_in[2];
    const float* W_lin  = (const float*)d_in[3];
    const float* b_lin  = (const float*)d_in[4];
    const float* W_conv = (const float*)d_in[5];
    const float* b_conv = (const float*)d_in[6];
    const float* W_lin2 = (const float*)d_in[7];
    const float* b_lin2 = (const float*)d_in[8];
    const float* Wa     = (const float*)d_in[9];
    const float* ba     = (const float*)d_in[10];
    const float* Wx     = (const float*)d_in[11];
    const float* bx     = (const float*)d_in[12];
    const float* Lam    = (const float*)d_in[13];
    const float* W1     = (const float*)d_in[14];
    const float* b1     = (const float*)d_in[15];
    const float* W2     = (const float*)d_in[16];
    const float* b2     = (const float*)d_in[17];
    const float* W3     = (const float*)d_in[18];
    const float* b3     = (const float*)d_in[19];
    float* out = (float*)d_out;

    float *xn, *lin, *rg, *rt, *it, *res;
    __nv_bfloat16 *Ah, *Al, *Wh, *Wl;
    cudaGetSymbolAddress((void**)&xn,  g_xn);
    cudaGetSymbolAddress((void**)&lin, g_lin);
    cudaGetSymbolAddress((void**)&rg,  g_rg);
    cudaGetSymbolAddress((void**)&rt,  g_rt);
    cudaGetSymbolAddress((void**)&it,  g_it);
    cudaGetSymbolAddress((void**)&res, g_res);
    cudaGetSymbolAddress((void**)&Ah,  g_Ah);
    cudaGetSymbolAddress((void**)&Al,  g_Al);
    cudaGetSymbolAddress((void**)&Wh,  g_Wh);
    cudaGetSymbolAddress((void**)&Wl,  g_Wl);

    const int GEMM_SMEM = NSTAGE * STAGE_BYTES + 1024;
    cudaFuncSetAttribute(mma_gemm_kernel,
                         cudaFuncAttributeMaxDynamicSharedMemorySize, GEMM_SMEM);

    dim3 gg(DDIM / 128, MROWS / 128);   // (8, 128)
    int ewBlocks = (MROWS * DDIM / 4 + 255) / 256;
    int aBlocks  = (MROWS * DDIM / 4 + 255) / 256;
    int wBlocks  = (DDIM * DDIM / 4 + 255) / 256;

    #define SPLIT_A(srcp) split_kernel<<<aBlocks, 256>>>(srcp, Ah, Al, MROWS * DDIM / 4)
    #define SPLIT_W(srcp) split_kernel<<<wBlocks, 256>>>(srcp, Wh, Wl, DDIM * DDIM / 4)
    #define GEMM(biasp, addq, outp, da) \
        mma_gemm_kernel<<<gg, 256, GEMM_SMEM>>>(Ah, Al, Wh, Wl, biasp, addq, outp, da)

    // 1) xn = rmsnorm(x, g1)
    rmsnorm_kernel<<<MROWS, 256>>>(x, g1, xn);
    // 2) lin = xn @ W_lin^T + b_lin
    SPLIT_A(xn); SPLIT_W(W_lin); GEMM(b_lin, x, lin, 0);
    // 3) rg = lin @ W_conv^T + b_conv
    SPLIT_A(lin); SPLIT_W(W_conv); GEMM(b_conv, x, rg, 0);
    // 4) rt = rg @ Wa^T + ba ; it = rg @ Wx^T + bx
    SPLIT_A(rg);
    SPLIT_W(Wa); GEMM(ba, x, rt, 0);
    SPLIT_W(Wx); GEMM(bx, x, it, 0);
    // 5) rt <- a, it <- gated
    gateprep_kernel<<<ewBlocks, 256>>>(rt, it, rg, Lam);
    // 6) rg <- scan(a, gated)
    scan_kernel<<<128, 32>>>(rt, it, rg);
    // 7) lin <- gelu(lin) * rg
    mult_kernel<<<ewBlocks, 256>>>(lin, rg);
    // 8) res = lin @ W_lin2^T + b_lin2 + x
    SPLIT_A(lin); SPLIT_W(W_lin2); GEMM(b_lin2, x, res, 1);
    // 9) xn = rmsnorm(res, g2)
    rmsnorm_kernel<<<MROWS, 256>>>(res, g2, xn);
    // 10) rt = xn @ W1^T + b1 ; it = xn @ W2^T + b2
    SPLIT_A(xn);
    SPLIT_W(W1); GEMM(b1, x, rt, 0);
    SPLIT_W(W2); GEMM(b2, x, it, 0);
    // 11) lin <- gelu(sigmoid(rt)) * it
    comb_kernel<<<ewBlocks, 256>>>(lin, rt, it);
    // 12) out = lin @ W3^T + b3 + res
    SPLIT_A(lin); SPLIT_W(W3); GEMM(b3, res, out, 1);

    (void)in_sizes; (void)n_in; (void)out_size;
}

// round 4
// speedup vs baseline: 3.0575x; 1.1358x over previous
#include <cuda_runtime.h>
#include <cuda_bf16.h>
#include <math.h>
#include <cstdint>

// Problem dims
#define MROWS 16384   // B*T = 4*4096
#define DDIM  1024
#define TLEN  4096
#define CHUNKS 32
#define CHLEN  (TLEN / CHUNKS)   // 128
#define NCHAIN 4096              // B * D

// ---------------- scratch (device globals; no allocation allowed) ----------
__device__ float g_lin[MROWS * DDIM];
__device__ float g_rg [MROWS * DDIM];
__device__ float g_rt [MROWS * DDIM];
__device__ float g_it [MROWS * DDIM];
__device__ float g_res[MROWS * DDIM];
__device__ float g_hl [MROWS * DDIM];
__device__ __nv_bfloat16 g_A0h[MROWS * DDIM];
__device__ __nv_bfloat16 g_A0l[MROWS * DDIM];
__device__ __nv_bfloat16 g_A1h[MROWS * DDIM];
__device__ __nv_bfloat16 g_A1l[MROWS * DDIM];
__device__ __nv_bfloat16 g_Wh[DDIM * DDIM];
__device__ __nv_bfloat16 g_Wl[DDIM * DDIM];
__device__ float g_Acar[NCHAIN * CHUNKS];
__device__ float g_Hcar[NCHAIN * CHUNKS];
__device__ float g_carry[NCHAIN * CHUNKS];

// ---------------- base-ISA tensor helpers ----------------------------------
__device__ __forceinline__ uint32_t smem_to_u32(const void* p) {
    uint32_t a;
    asm("{ .reg .u64 t; cvta.to.shared.u64 t, %1; cvt.u32.u64 %0, t; }"
        : "=r"(a) : "l"(p));
    return a;
}
__device__ __forceinline__ void cpasync16(uint32_t dst, const void* src) {
    asm volatile("cp.async.cg.shared.global [%0], [%1], 16;"
                 :: "r"(dst), "l"(src) : "memory");
}
#define CP_COMMIT() asm volatile("cp.async.commit_group;" ::: "memory")
#define CP_WAIT(n)  asm volatile("cp.async.wait_group %0;" :: "n"(n) : "memory")

__device__ __forceinline__ void ldsm4(uint32_t addr, uint32_t* r) {
    asm volatile("ldmatrix.sync.aligned.m8n8.x4.shared.b16 {%0,%1,%2,%3}, [%4];"
                 : "=r"(r[0]), "=r"(r[1]), "=r"(r[2]), "=r"(r[3]) : "r"(addr));
}
__device__ __forceinline__ void mma16816(float* c, const uint32_t* a, const uint32_t* b) {
    asm volatile(
        "mma.sync.aligned.m16n8k16.row.col.f32.bf16.bf16.f32 "
        "{%0,%1,%2,%3}, {%4,%5,%6,%7}, {%8,%9}, {%0,%1,%2,%3};"
        : "+f"(c[0]), "+f"(c[1]), "+f"(c[2]), "+f"(c[3])
        : "r"(a[0]), "r"(a[1]), "r"(a[2]), "r"(a[3]), "r"(b[0]), "r"(b[1]));
}

// ---------------- math helpers ---------------------------------------------
__device__ __forceinline__ float gelu_exact(float x) {
    return 0.5f * x * (1.0f + erff(x * 0.70710678118654752440f));
}
__device__ __forceinline__ float sigmoidf_(float x) {
    return 1.0f / (1.0f + expf(-x));
}
__device__ __forceinline__ void split2(float a, float b,
                                       __nv_bfloat162& h, __nv_bfloat162& l) {
    h = __floats2bfloat162_rn(a, b);
    l = __floats2bfloat162_rn(a - __low2float(h), b - __high2float(h));
}

// ---------------- fp32 -> (hi, lo) bf16 split (weights) --------------------
__global__ void split_kernel(const float* __restrict__ src,
                             __nv_bfloat16* __restrict__ hi,
                             __nv_bfloat16* __restrict__ lo, int n4) {
    int i = blockIdx.x * 256 + threadIdx.x;
    if (i >= n4) return;
    float4 v = ((const float4*)src)[i];
    __nv_bfloat162 h01, l01, h23, l23;
    split2(v.x, v.y, h01, l01);
    split2(v.z, v.w, h23, l23);
    ((__nv_bfloat162*)hi)[2 * i]     = h01;
    ((__nv_bfloat162*)hi)[2 * i + 1] = h23;
    ((__nv_bfloat162*)lo)[2 * i]     = l01;
    ((__nv_bfloat162*)lo)[2 * i + 1] = l23;
}

// ---------------- split-bf16 mma.sync GEMM ---------------------------------
// C[M,N] = (Ah+Al)[M,K] @ (Bh+Bl)[N,K]^T + bias (+ add), fp32 accumulate.
// CTA tile 128x128, K-chunk 64, 3-stage cp.async pipeline, 256 threads.
// Optional bf16-split output for feeding the next GEMM.
#define TILE_BYTES  16384            // 128 x 64 bf16
#define STAGE_BYTES 65536            // 4 tiles: Ah, Al, Bh, Bl
#define NSTAGE 3
#define NCHUNK (DDIM / 64)           // 16

__device__ __forceinline__ uint32_t swaddr(uint32_t tile, uint32_t row, uint32_t kb) {
    uint32_t off = row * 128u + kb;
    return tile + (off ^ ((off >> 3) & 0x70u));
}

__global__ void __launch_bounds__(256, 1)
mma_gemm_kernel(const __nv_bfloat16* __restrict__ Ah, const __nv_bfloat16* __restrict__ Al,
                const __nv_bfloat16* __restrict__ Bh, const __nv_bfloat16* __restrict__ Bl,
                const float* __restrict__ bias, const float* __restrict__ addp,
                float* __restrict__ C, int doAdd,
                __nv_bfloat16* __restrict__ Sh, __nv_bfloat16* __restrict__ Sl) {
    extern __shared__ __align__(1024) char smem_raw[];
    uint32_t smem0 = smem_to_u32(smem_raw);
    uint32_t tbase = (smem0 + 1023u) & ~1023u;

    int tid = threadIdx.x;
    int wid = tid >> 5;
    int lane = tid & 31;
    int m0 = blockIdx.y * 128;
    int n0 = blockIdx.x * 128;

    // ---- producer mapping ----
    int row_base = tid >> 3;
    int col = tid & 7;
    const char* srcb[16];
    uint32_t stsoff[16];
    {
        const char* base4[4];
        base4[0] = (const char*)(Ah + (size_t)m0 * DDIM);
        base4[1] = (const char*)(Al + (size_t)m0 * DDIM);
        base4[2] = (const char*)(Bh + (size_t)n0 * DDIM);
        base4[3] = (const char*)(Bl + (size_t)n0 * DDIM);
        #pragma unroll
        for (int i = 0; i < 16; i++) {
            uint32_t rr = (uint32_t)row_base + 32u * (i & 3);
            srcb[i] = base4[i >> 2] + (size_t)rr * 2048 + col * 16;
            uint32_t off = rr * 128u + (uint32_t)col * 16u;
            stsoff[i] = (uint32_t)(i >> 2) * TILE_BYTES + (off ^ ((off >> 3) & 0x70u));
        }
    }

    #define ISSUE_STAGE(buf, chunk) do { \
        uint32_t db_ = tbase + (uint32_t)(buf) * STAGE_BYTES; \
        _Pragma("unroll") \
        for (int i_ = 0; i_ < 16; i_++) \
            cpasync16(db_ + stsoff[i_], srcb[i_] + (size_t)(chunk) * 128); \
        CP_COMMIT(); \
    } while (0)

    // ---- consumer mapping ----
    int warp_m = wid & 3;
    int warp_n = wid >> 2;
    uint32_t ar  = (uint32_t)((lane & 7) + ((lane >> 3) & 1) * 8);
    uint32_t akb = (uint32_t)(((lane >> 4) & 1) * 16);
    uint32_t br  = (uint32_t)((lane & 7) + ((lane >> 4) & 1) * 8);
    uint32_t bkb = (uint32_t)(((lane >> 3) & 1) * 16);

    float acc[2][8][4];
    #pragma unroll
    for (int i = 0; i < 2; i++)
        #pragma unroll
        for (int j = 0; j < 8; j++)
            #pragma unroll
            for (int q = 0; q < 4; q++) acc[i][j][q] = 0.0f;

    ISSUE_STAGE(0, 0);
    ISSUE_STAGE(1, 1);

    for (int c = 0; c < NCHUNK; c++) {
        if (c < NCHUNK - 1) { CP_WAIT(1); } else { CP_WAIT(0); }
        __syncthreads();
        if (c + 2 < NCHUNK) ISSUE_STAGE((c + 2) % NSTAGE, c + 2);

        uint32_t sb = tbase + (uint32_t)(c % NSTAGE) * STAGE_BYTES;
        uint32_t tAh = sb;
        uint32_t tAl = sb + TILE_BYTES;
        uint32_t tBh = sb + 2 * TILE_BYTES;
        uint32_t tBl = sb + 3 * TILE_BYTES;

        #pragma unroll
        for (int k16 = 0; k16 < 4; k16++) {
            uint32_t kb = (uint32_t)k16 * 32u;
            uint32_t ah[2][4], al[2][4], bh[4][4], bl[4][4];
            #pragma unroll
            for (int mt = 0; mt < 2; mt++)
                ldsm4(swaddr(tAh, (uint32_t)(warp_m * 32 + mt * 16) + ar, kb + akb), ah[mt]);
            #pragma unroll
            for (int p = 0; p < 4; p++)
                ldsm4(swaddr(tBh, (uint32_t)(warp_n * 64 + p * 16) + br, kb + bkb), bh[p]);
            #pragma unroll
            for (int mt = 0; mt < 2; mt++)
                #pragma unroll
                for (int p = 0; p < 4; p++) {
                    mma16816(acc[mt][2 * p],     ah[mt], &bh[p][0]);
                    mma16816(acc[mt][2 * p + 1], ah[mt], &bh[p][2]);
                }
            #pragma unroll
            for (int p = 0; p < 4; p++)
                ldsm4(swaddr(tBl, (uint32_t)(warp_n * 64 + p * 16) + br, kb + bkb), bl[p]);
            #pragma unroll
            for (int mt = 0; mt < 2; mt++)
                #pragma unroll
                for (int p = 0; p < 4; p++) {
                    mma16816(acc[mt][2 * p],     ah[mt], &bl[p][0]);
                    mma16816(acc[mt][2 * p + 1], ah[mt], &bl[p][2]);
                }
            #pragma unroll
            for (int mt = 0; mt < 2; mt++)
                ldsm4(swaddr(tAl, (uint32_t)(warp_m * 32 + mt * 16) + ar, kb + akb), al[mt]);
            #pragma unroll
            for (int mt = 0; mt < 2; mt++)
                #pragma unroll
                for (int p = 0; p < 4; p++) {
                    mma16816(acc[mt][2 * p],     al[mt], &bh[p][0]);
                    mma16816(acc[mt][2 * p + 1], al[mt], &bh[p][2]);
                }
        }
    }

    // ---- epilogue ----
    int lm = lane >> 2;
    int lc = (lane & 3) * 2;
    int cm = m0 + warp_m * 32;
    int cn = n0 + warp_n * 64;
    #pragma unroll
    for (int mt = 0; mt < 2; mt++) {
        #pragma unroll
        for (int nt = 0; nt < 8; nt++) {
            int r0 = cm + mt * 16 + lm;
            int cc = cn + nt * 8 + lc;
            float2 bv = *(const float2*)&bias[cc];
            float* a = acc[mt][nt];
            float2 o0 = make_float2(a[0] + bv.x, a[1] + bv.y);
            float2 o1 = make_float2(a[2] + bv.x, a[3] + bv.y);
            size_t off0 = (size_t)r0 * DDIM + cc;
            size_t off1 = (size_t)(r0 + 8) * DDIM + cc;
            if (doAdd) {
                float2 q0 = *(const float2*)(addp + off0);
                float2 q1 = *(const float2*)(addp + off1);
                o0.x += q0.x; o0.y += q0.y;
                o1.x += q1.x; o1.y += q1.y;
            }
            *(float2*)(C + off0) = o0;
            *(float2*)(C + off1) = o1;
            if (Sh) {
                __nv_bfloat162 h0, l0, h1, l1;
                split2(o0.x, o0.y, h0, l0);
                split2(o1.x, o1.y, h1, l1);
                *(__nv_bfloat162*)(Sh + off0) = h0;
                *(__nv_bfloat162*)(Sl + off0) = l0;
                *(__nv_bfloat162*)(Sh + off1) = h1;
                *(__nv_bfloat162*)(Sl + off1) = l1;
            }
        }
    }
}

// ---------------- rmsnorm -> bf16 split ------------------------------------
__global__ void rmsnorm_split_kernel(const float* __restrict__ x,
                                     const float* __restrict__ gw,
                                     __nv_bfloat16* __restrict__ Sh,
                                     __nv_bfloat16* __restrict__ Sl) {
    int row = blockIdx.x;
    const float4* xr = (const float4*)(x + (size_t)row * DDIM);
    float4 v = xr[threadIdx.x];
    float ss = v.x * v.x + v.y * v.y + v.z * v.z + v.w * v.w;
    #pragma unroll
    for (int o = 16; o > 0; o >>= 1) ss += __shfl_xor_sync(0xffffffffu, ss, o);
    __shared__ float sred[8];
    if ((threadIdx.x & 31) == 0) sred[threadIdx.x >> 5] = ss;
    __syncthreads();
    float total = 0.0f;
    #pragma unroll
    for (int i = 0; i < 8; i++) total += sred[i];
    float n = fmaxf(sqrtf(total), 1e-12f);
    float s = 32.0f / n;
    float4 g = ((const float4*)gw)[threadIdx.x];
    float o0 = v.x * s * g.x, o1 = v.y * s * g.y;
    float o2 = v.z * s * g.z, o3 = v.w * s * g.w;
    __nv_bfloat162 h01, l01, h23, l23;
    split2(o0, o1, h01, l01);
    split2(o2, o3, h23, l23);
    size_t base2 = (size_t)row * (DDIM / 2) + threadIdx.x * 2;
    ((__nv_bfloat162*)Sh)[base2]     = h01;
    ((__nv_bfloat162*)Sh)[base2 + 1] = h23;
    ((__nv_bfloat162*)Sl)[base2]     = l01;
    ((__nv_bfloat162*)Sl)[base2 + 1] = l23;
}

// ---------------- chunked RG-LRU scan --------------------------------------
// pass 1: fused gate computation + per-chunk local scan
__global__ void scan1_kernel(const float* __restrict__ rt, const float* __restrict__ it,
                             const float* __restrict__ rg, const float* __restrict__ Lam,
                             float* __restrict__ hl,
                             float* __restrict__ Acar, float* __restrict__ Hcar) {
    int i = blockIdx.x * 256 + threadIdx.x;     // 0 .. 131071
    int chain = i & (NCHAIN - 1);
    int chunk = i >> 12;
    int b = chain >> 10, d = chain & (DDIM - 1);
    size_t base = ((size_t)b * TLEN + (size_t)chunk * CHLEN) * DDIM + d;
    float la = -log1pf(expf(-Lam[d]));
    float h = 0.0f, P = 1.0f;
    for (int t = 0; t < CHLEN; t++) {
        size_t a_ = base + (size_t)t * DDIM;
        float r  = rt[a_];
        float iv = it[a_];
        float xv = rg[a_];
        float a = expf(la * sigmoidf_(r) * 0.125f);
        float g = sqrtf(fmaxf(1.0f - a * a, 0.0f)) * sigmoidf_(iv) * xv;
        h = fmaf(a, h, g);
        P *= a;
        hl[a_] = h;
    }
    Acar[i] = P;
    Hcar[i] = h;
}

// pass 2: serial scan over chunk aggregates (per chain)
__global__ void scan2_kernel(const float* __restrict__ Acar, const float* __restrict__ Hcar,
                             float* __restrict__ carry) {
    int chain = blockIdx.x * 256 + threadIdx.x;   // 0..4095
    float h = 0.0f;
    #pragma unroll
    for (int c = 0; c < CHUNKS; c++) {
        int idx = c * NCHAIN + chain;
        carry[idx] = h;
        h = fmaf(Acar[idx], h, Hcar[idx]);
    }
}

// pass 3: apply carry, fused gelu(lin)*h, write bf16 split
__global__ void scan3_kernel(const float* __restrict__ rt, const float* __restrict__ hl,
                             const float* __restrict__ carry, const float* __restrict__ lin,
                             const float* __restrict__ Lam,
                             __nv_bfloat16* __restrict__ Sh, __nv_bfloat16* __restrict__ Sl) {
    int i = blockIdx.x * 256 + threadIdx.x;
    int chain = i & (NCHAIN - 1);
    int chunk = i >> 12;
    int b = chain >> 10, d = chain & (DDIM - 1);
    size_t base = ((size_t)b * TLEN + (size_t)chunk * CHLEN) * DDIM + d;
    float la = -log1pf(expf(-Lam[d]));
    float cin = carry[i];
    float P = 1.0f;
    for (int t = 0; t < CHLEN; t++) {
        size_t a_ = base + (size_t)t * DDIM;
        float r = rt[a_];
        float a = expf(la * sigmoidf_(r) * 0.125f);
        P *= a;
        float h = fmaf(P, cin, hl[a_]);
        float l = lin[a_];
        float o = gelu_exact(l) * h;
        __nv_bfloat16 bh = __float2bfloat16_rn(o);
        __nv_bfloat16 bl = __float2bfloat16_rn(o - __bfloat162float(bh));
        Sh[a_] = bh;
        Sl[a_] = bl;
    }
}

// ---------------- gelu(sigmoid(t1)) * t2 -> bf16 split ---------------------
__global__ void comb_split_kernel(const float* __restrict__ t1,
                                  const float* __restrict__ t2,
                                  __nv_bfloat16* __restrict__ Sh,
                                  __nv_bfloat16* __restrict__ Sl) {
    int i = blockIdx.x * blockDim.x + threadIdx.x;
    if (i >= MROWS * DDIM / 4) return;
    float4 a = ((const float4*)t1)[i];
    float4 b = ((const float4*)t2)[i];
    float o0 = gelu_exact(sigmoidf_(a.x)) * b.x;
    float o1 = gelu_exact(sigmoidf_(a.y)) * b.y;
    float o2 = gelu_exact(sigmoidf_(a.z)) * b.z;
    float o3 = gelu_exact(sigmoidf_(a.w)) * b.w;
    __nv_bfloat162 h01, l01, h23, l23;
    split2(o0, o1, h01, l01);
    split2(o2, o3, h23, l23);
    ((__nv_bfloat162*)Sh)[2 * i]     = h01;
    ((__nv_bfloat162*)Sh)[2 * i + 1] = h23;
    ((__nv_bfloat162*)Sl)[2 * i]     = l01;
    ((__nv_bfloat162*)Sl)[2 * i + 1] = l23;
}

// ---------------- launch ---------------------------------------------------
extern "C" void kernel_launch(void* const* d_in, const int* in_sizes, int n_in,
                              void* d_out, int out_size) {
    const float* x      = (const float*)d_in[0];
    const float* g1     = (const float*)d_in[1];
    const float* g2     = (const float*)d_in[2];
    const float* W_lin  = (const float*)d_in[3];
    const float* b_lin  = (const float*)d_in[4];
    const float* W_conv = (const float*)d_in[5];
    const float* b_conv = (const float*)d_in[6];
    const float* W_lin2 = (const float*)d_in[7];
    const float* b_lin2 = (const float*)d_in[8];
    const float* Wa     = (const float*)d_in[9];
    const float* ba     = (const float*)d_in[10];
    const float* Wx     = (const float*)d_in[11];
    const float* bx     = (const float*)d_in[12];
    const float* Lam    = (const float*)d_in[13];
    const float* W1     = (const float*)d_in[14];
    const float* b1     = (const float*)d_in[15];
    const float* W2     = (const float*)d_in[16];
    const float* b2     = (const float*)d_in[17];
    const float* W3     = (const float*)d_in[18];
    const float* b3     = (const float*)d_in[19];
    float* out = (float*)d_out;

    float *lin, *rg, *rt, *it, *res, *hl, *Acar, *Hcar, *carry;
    __nv_bfloat16 *A0h, *A0l, *A1h, *A1l, *Wh, *Wl;
    cudaGetSymbolAddress((void**)&lin, g_lin);
    cudaGetSymbolAddress((void**)&rg,  g_rg);
    cudaGetSymbolAddress((void**)&rt,  g_rt);
    cudaGetSymbolAddress((void**)&it,  g_it);
    cudaGetSymbolAddress((void**)&res, g_res);
    cudaGetSymbolAddress((void**)&hl,  g_hl);
    cudaGetSymbolAddress((void**)&Acar, g_Acar);
    cudaGetSymbolAddress((void**)&Hcar, g_Hcar);
    cudaGetSymbolAddress((void**)&carry, g_carry);
    cudaGetSymbolAddress((void**)&A0h, g_A0h);
    cudaGetSymbolAddress((void**)&A0l, g_A0l);
    cudaGetSymbolAddress((void**)&A1h, g_A1h);
    cudaGetSymbolAddress((void**)&A1l, g_A1l);
    cudaGetSymbolAddress((void**)&Wh,  g_Wh);
    cudaGetSymbolAddress((void**)&Wl,  g_Wl);

    const int GEMM_SMEM = NSTAGE * STAGE_BYTES + 1024;
    cudaFuncSetAttribute(mma_gemm_kernel,
                         cudaFuncAttributeMaxDynamicSharedMemorySize, GEMM_SMEM);

    dim3 gg(DDIM / 128, MROWS / 128);   // (8, 128)
    int ewBlocks  = (MROWS * DDIM / 4 + 255) / 256;
    int wBlocks   = (DDIM * DDIM / 4 + 255) / 256;
    int scBlocks  = (NCHAIN * CHUNKS) / 256;   // 512

    #define SPLIT_W(srcp) split_kernel<<<wBlocks, 256>>>(srcp, Wh, Wl, DDIM * DDIM / 4)
    #define GEMM(inH, inL, biasp, addq, outp, da, sh, sl) \
        mma_gemm_kernel<<<gg, 256, GEMM_SMEM>>>(inH, inL, Wh, Wl, biasp, addq, outp, da, sh, sl)

    // 1) A0 = split(rmsnorm(x, g1))
    rmsnorm_split_kernel<<<MROWS, 256>>>(x, g1, A0h, A0l);
    // 2) lin = xn @ W_lin^T + b_lin ; A1 = split(lin)
    SPLIT_W(W_lin); GEMM(A0h, A0l, b_lin, x, lin, 0, A1h, A1l);
    // 3) rg = lin @ W_conv^T + b_conv ; A0 = split(rg)
    SPLIT_W(W_conv); GEMM(A1h, A1l, b_conv, x, rg, 0, A0h, A0l);
    // 4) rt = rg @ Wa^T + ba ; it = rg @ Wx^T + bx
    SPLIT_W(Wa); GEMM(A0h, A0l, ba, x, rt, 0, (__nv_bfloat16*)nullptr, (__nv_bfloat16*)nullptr);
    SPLIT_W(Wx); GEMM(A0h, A0l, bx, x, it, 0, (__nv_bfloat16*)nullptr, (__nv_bfloat16*)nullptr);
    // 5-7) chunked scan with fused gateprep + fused gelu(lin)*h + split
    scan1_kernel<<<scBlocks, 256>>>(rt, it, rg, Lam, hl, Acar, Hcar);
    scan2_kernel<<<NCHAIN / 256, 256>>>(Acar, Hcar, carry);
    scan3_kernel<<<scBlocks, 256>>>(rt, hl, carry, lin, Lam, A1h, A1l);
    // 8) res = (gelu(lin)*h) @ W_lin2^T + b_lin2 + x
    SPLIT_W(W_lin2); GEMM(A1h, A1l, b_lin2, x, res, 1, (__nv_bfloat16*)nullptr, (__nv_bfloat16*)nullptr);
    // 9) A0 = split(rmsnorm(res, g2))
    rmsnorm_split_kernel<<<MROWS, 256>>>(res, g2, A0h, A0l);
    // 10) rt = xm @ W1^T + b1 ; it = xm @ W2^T + b2
    SPLIT_W(W1); GEMM(A0h, A0l, b1, x, rt, 0, (__nv_bfloat16*)nullptr, (__nv_bfloat16*)nullptr);
    SPLIT_W(W2); GEMM(A0h, A0l, b2, x, it, 0, (__nv_bfloat16*)nullptr, (__nv_bfloat16*)nullptr);
    // 11) A1 = split(gelu(sigmoid(rt)) * it)
    comb_split_kernel<<<ewBlocks, 256>>>(rt, it, A1h, A1l);
    // 12) out = combined @ W3^T + b3 + res
    SPLIT_W(W3); GEMM(A1h, A1l, b3, res, out, 1, (__nv_bfloat16*)nullptr, (__nv_bfloat16*)nullptr);

    (void)in_sizes; (void)n_in; (void)out_size;
}

// round 5
// speedup vs baseline: 3.1370x; 1.0260x over previous
#include <cuda_runtime.h>
#include <cuda_bf16.h>
#include <math.h>
#include <cstdint>

// Problem dims
#define MROWS 16384   // B*T = 4*4096
#define DDIM  1024
#define TLEN  4096
#define CHUNKS 32
#define CHLEN  (TLEN / CHUNKS)   // 128
#define NCHAIN 4096              // B * D

// ---------------- scratch (device globals; no allocation allowed) ----------
__device__ float g_lin[MROWS * DDIM];
__device__ float g_rg [MROWS * DDIM];
__device__ float g_rt [MROWS * DDIM];
__device__ float g_it [MROWS * DDIM];
__device__ float g_res[MROWS * DDIM];
__device__ float g_hl [MROWS * DDIM];
__device__ __nv_bfloat16 g_A0h[MROWS * DDIM];
__device__ __nv_bfloat16 g_A0l[MROWS * DDIM];
__device__ __nv_bfloat16 g_A1h[MROWS * DDIM];
__device__ __nv_bfloat16 g_A1l[MROWS * DDIM];
__device__ __nv_bfloat16 g_Wh[DDIM * DDIM];
__device__ __nv_bfloat16 g_Wl[DDIM * DDIM];
__device__ float g_Acar[NCHAIN * CHUNKS];
__device__ float g_Hcar[NCHAIN * CHUNKS];
__device__ float g_carry[NCHAIN * CHUNKS];

// ---------------- base-ISA tensor helpers ----------------------------------
__device__ __forceinline__ uint32_t smem_to_u32(const void* p) {
    uint32_t a;
    asm("{ .reg .u64 t; cvta.to.shared.u64 t, %1; cvt.u32.u64 %0, t; }"
        : "=r"(a) : "l"(p));
    return a;
}
__device__ __forceinline__ void cpasync16(uint32_t dst, const void* src) {
    asm volatile("cp.async.cg.shared.global [%0], [%1], 16;"
                 :: "r"(dst), "l"(src) : "memory");
}
#define CP_COMMIT() asm volatile("cp.async.commit_group;" ::: "memory")
#define CP_WAIT(n)  asm volatile("cp.async.wait_group %0;" :: "n"(n) : "memory")

__device__ __forceinline__ void ldsm4(uint32_t addr, uint32_t* r) {
    asm volatile("ldmatrix.sync.aligned.m8n8.x4.shared.b16 {%0,%1,%2,%3}, [%4];"
                 : "=r"(r[0]), "=r"(r[1]), "=r"(r[2]), "=r"(r[3]) : "r"(addr));
}
__device__ __forceinline__ void mma16816(float* c, const uint32_t* a, const uint32_t* b) {
    asm volatile(
        "mma.sync.aligned.m16n8k16.row.col.f32.bf16.bf16.f32 "
        "{%0,%1,%2,%3}, {%4,%5,%6,%7}, {%8,%9}, {%0,%1,%2,%3};"
        : "+f"(c[0]), "+f"(c[1]), "+f"(c[2]), "+f"(c[3])
        : "r"(a[0]), "r"(a[1]), "r"(a[2]), "r"(a[3]), "r"(b[0]), "r"(b[1]));
}

// ---------------- math helpers ---------------------------------------------
__device__ __forceinline__ float gelu_exact(float x) {
    return 0.5f * x * (1.0f + erff(x * 0.70710678118654752440f));
}
__device__ __forceinline__ float sigmoidf_(float x) {
    return 1.0f / (1.0f + expf(-x));
}
__device__ __forceinline__ void split2(float a, float b,
                                       __nv_bfloat162& h, __nv_bfloat162& l) {
    h = __floats2bfloat162_rn(a, b);
    l = __floats2bfloat162_rn(a - __low2float(h), b - __high2float(h));
}

// ---------------- fp32 -> (hi, lo) bf16 split (weights) --------------------
__global__ void split_kernel(const float* __restrict__ src,
                             __nv_bfloat16* __restrict__ hi,
                             __nv_bfloat16* __restrict__ lo, int n4) {
    int i = blockIdx.x * 256 + threadIdx.x;
    if (i >= n4) return;
    float4 v = ((const float4*)src)[i];
    __nv_bfloat162 h01, l01, h23, l23;
    split2(v.x, v.y, h01, l01);
    split2(v.z, v.w, h23, l23);
    ((__nv_bfloat162*)hi)[2 * i]     = h01;
    ((__nv_bfloat162*)hi)[2 * i + 1] = h23;
    ((__nv_bfloat162*)lo)[2 * i]     = l01;
    ((__nv_bfloat162*)lo)[2 * i + 1] = l23;
}

// ---------------- split-bf16 mma.sync GEMM ---------------------------------
// C[M,N] = (Ah+Al)[M,K] @ (Bh+Bl)[N,K]^T + bias (+ add), fp32 accumulate.
// CTA tile 128x64, K-chunk 64, 2-stage cp.async pipeline, 256 threads,
// 2 CTAs/SM. Optional bf16-split output for feeding the next GEMM.
#define TILE_A_BYTES 16384           // 128 x 64 bf16
#define TILE_B_BYTES 8192            // 64 x 64 bf16
#define STAGE_BYTES  49152           // Ah, Al, Bh, Bl
#define NSTAGE 2
#define NCHUNK (DDIM / 64)           // 16

__device__ __forceinline__ uint32_t swaddr(uint32_t tile, uint32_t row, uint32_t kb) {
    uint32_t off = row * 128u + kb;
    return tile + (off ^ ((off >> 3) & 0x70u));
}

__global__ void __launch_bounds__(256, 2)
mma_gemm_kernel(const __nv_bfloat16* __restrict__ Ah, const __nv_bfloat16* __restrict__ Al,
                const __nv_bfloat16* __restrict__ Bh, const __nv_bfloat16* __restrict__ Bl,
                const float* __restrict__ bias, const float* __restrict__ addp,
                float* __restrict__ C, int doAdd,
                __nv_bfloat16* __restrict__ Sh, __nv_bfloat16* __restrict__ Sl) {
    extern __shared__ __align__(1024) char smem_raw[];
    uint32_t smem0 = smem_to_u32(smem_raw);
    uint32_t tbase = (smem0 + 1023u) & ~1023u;

    int tid = threadIdx.x;
    int wid = tid >> 5;
    int lane = tid & 31;
    int m0 = blockIdx.y * 128;
    int n0 = blockIdx.x * 64;

    // ---- producer mapping: 12 x 16B vecs per thread per stage ----
    // i 0..7  : A tiles (Ah i>>2==0, Al i>>2==1), rows (tid>>3)+32*(i&3)
    // i 8..11 : B tiles (Bh (i-8)>>1==0, Bl ==1), rows (tid>>3)+32*((i-8)&1)
    int row_base = tid >> 3;
    int col = tid & 7;
    const char* srcb[12];
    uint32_t stsoff[12];
    {
        const char* aBase[2] = { (const char*)(Ah + (size_t)m0 * DDIM),
                                 (const char*)(Al + (size_t)m0 * DDIM) };
        const char* bBase[2] = { (const char*)(Bh + (size_t)n0 * DDIM),
                                 (const char*)(Bl + (size_t)n0 * DDIM) };
        #pragma unroll
        for (int i = 0; i < 8; i++) {
            uint32_t rr = (uint32_t)row_base + 32u * (i & 3);
            srcb[i] = aBase[i >> 2] + (size_t)rr * 2048 + col * 16;
            uint32_t off = rr * 128u + (uint32_t)col * 16u;
            stsoff[i] = (uint32_t)(i >> 2) * TILE_A_BYTES + (off ^ ((off >> 3) & 0x70u));
        }
        #pragma unroll
        for (int i = 8; i < 12; i++) {
            uint32_t rr = (uint32_t)row_base + 32u * ((i - 8) & 1);
            srcb[i] = bBase[(i - 8) >> 1] + (size_t)rr * 2048 + col * 16;
            uint32_t off = rr * 128u + (uint32_t)col * 16u;
            stsoff[i] = 2u * TILE_A_BYTES + (uint32_t)((i - 8) >> 1) * TILE_B_BYTES
                        + (off ^ ((off >> 3) & 0x70u));
        }
    }

    #define ISSUE_STAGE(buf, chunk) do { \
        uint32_t db_ = tbase + (uint32_t)(buf) * STAGE_BYTES; \
        _Pragma("unroll") \
        for (int i_ = 0; i_ < 12; i_++) \
            cpasync16(db_ + stsoff[i_], srcb[i_] + (size_t)(chunk) * 128); \
        CP_COMMIT(); \
    } while (0)

    // ---- consumer mapping: 8 warps, warp tile 32x32 (4 M x 2 N) ----
    int warp_m = wid & 3;
    int warp_n = wid >> 2;
    uint32_t ar  = (uint32_t)((lane & 7) + ((lane >> 3) & 1) * 8);
    uint32_t akb = (uint32_t)(((lane >> 4) & 1) * 16);
    uint32_t br  = (uint32_t)((lane & 7) + ((lane >> 4) & 1) * 8);
    uint32_t bkb = (uint32_t)(((lane >> 3) & 1) * 16);

    float acc[2][4][4];
    #pragma unroll
    for (int i = 0; i < 2; i++)
        #pragma unroll
        for (int j = 0; j < 4; j++)
            #pragma unroll
            for (int q = 0; q < 4; q++) acc[i][j][q] = 0.0f;

    ISSUE_STAGE(0, 0);

    for (int c = 0; c < NCHUNK; c++) {
        CP_WAIT(0);
        __syncthreads();
        if (c + 1 < NCHUNK) ISSUE_STAGE((c + 1) & 1, c + 1);

        uint32_t sb = tbase + (uint32_t)(c & 1) * STAGE_BYTES;
        uint32_t tAh = sb;
        uint32_t tAl = sb + TILE_A_BYTES;
        uint32_t tBh = sb + 2 * TILE_A_BYTES;
        uint32_t tBl = sb + 2 * TILE_A_BYTES + TILE_B_BYTES;

        #pragma unroll
        for (int k16 = 0; k16 < 4; k16++) {
            uint32_t kb = (uint32_t)k16 * 32u;
            uint32_t ah[2][4], al[2][4], bh[2][4], bl[2][4];
            #pragma unroll
            for (int mt = 0; mt < 2; mt++)
                ldsm4(swaddr(tAh, (uint32_t)(warp_m * 32 + mt * 16) + ar, kb + akb), ah[mt]);
            #pragma unroll
            for (int p = 0; p < 2; p++)
                ldsm4(swaddr(tBh, (uint32_t)(warp_n * 32 + p * 16) + br, kb + bkb), bh[p]);
            // term 1: Ah @ Bh
            #pragma unroll
            for (int mt = 0; mt < 2; mt++)
                #pragma unroll
                for (int p = 0; p < 2; p++) {
                    mma16816(acc[mt][2 * p],     ah[mt], &bh[p][0]);
                    mma16816(acc[mt][2 * p + 1], ah[mt], &bh[p][2]);
                }
            // term 2: Ah @ Bl
            #pragma unroll
            for (int p = 0; p < 2; p++)
                ldsm4(swaddr(tBl, (uint32_t)(warp_n * 32 + p * 16) + br, kb + bkb), bl[p]);
            #pragma unroll
            for (int mt = 0; mt < 2; mt++)
                #pragma unroll
                for (int p = 0; p < 2; p++) {
                    mma16816(acc[mt][2 * p],     ah[mt], &bl[p][0]);
                    mma16816(acc[mt][2 * p + 1], ah[mt], &bl[p][2]);
                }
            // term 3: Al @ Bh
            #pragma unroll
            for (int mt = 0; mt < 2; mt++)
                ldsm4(swaddr(tAl, (uint32_t)(warp_m * 32 + mt * 16) + ar, kb + akb), al[mt]);
            #pragma unroll
            for (int mt = 0; mt < 2; mt++)
                #pragma unroll
                for (int p = 0; p < 2; p++) {
                    mma16816(acc[mt][2 * p],     al[mt], &bh[p][0]);
                    mma16816(acc[mt][2 * p + 1], al[mt], &bh[p][2]);
                }
        }
    }

    // ---- epilogue ----
    int lm = lane >> 2;
    int lc = (lane & 3) * 2;
    int cm = m0 + warp_m * 32;
    int cn = n0 + warp_n * 32;
    #pragma unroll
    for (int mt = 0; mt < 2; mt++) {
        #pragma unroll
        for (int nt = 0; nt < 4; nt++) {
            int r0 = cm + mt * 16 + lm;
            int cc = cn + nt * 8 + lc;
            float2 bv = *(const float2*)&bias[cc];
            float* a = acc[mt][nt];
            float2 o0 = make_float2(a[0] + bv.x, a[1] + bv.y);
            float2 o1 = make_float2(a[2] + bv.x, a[3] + bv.y);
            size_t off0 = (size_t)r0 * DDIM + cc;
            size_t off1 = (size_t)(r0 + 8) * DDIM + cc;
            if (doAdd) {
                float2 q0 = *(const float2*)(addp + off0);
                float2 q1 = *(const float2*)(addp + off1);
                o0.x += q0.x; o0.y += q0.y;
                o1.x += q1.x; o1.y += q1.y;
            }
            *(float2*)(C + off0) = o0;
            *(float2*)(C + off1) = o1;
            if (Sh) {
                __nv_bfloat162 h0, l0, h1, l1;
                split2(o0.x, o0.y, h0, l0);
                split2(o1.x, o1.y, h1, l1);
                *(__nv_bfloat162*)(Sh + off0) = h0;
                *(__nv_bfloat162*)(Sl + off0) = l0;
                *(__nv_bfloat162*)(Sh + off1) = h1;
                *(__nv_bfloat162*)(Sl + off1) = l1;
            }
        }
    }
}

// ---------------- rmsnorm -> bf16 split ------------------------------------
__global__ void rmsnorm_split_kernel(const float* __restrict__ x,
                                     const float* __restrict__ gw,
                                     __nv_bfloat16* __restrict__ Sh,
                                     __nv_bfloat16* __restrict__ Sl) {
    int row = blockIdx.x;
    const float4* xr = (const float4*)(x + (size_t)row * DDIM);
    float4 v = xr[threadIdx.x];
    float ss = v.x * v.x + v.y * v.y + v.z * v.z + v.w * v.w;
    #pragma unroll
    for (int o = 16; o > 0; o >>= 1) ss += __shfl_xor_sync(0xffffffffu, ss, o);
    __shared__ float sred[8];
    if ((threadIdx.x & 31) == 0) sred[threadIdx.x >> 5] = ss;
    __syncthreads();
    float total = 0.0f;
    #pragma unroll
    for (int i = 0; i < 8; i++) total += sred[i];
    float n = fmaxf(sqrtf(total), 1e-12f);
    float s = 32.0f / n;
    float4 g = ((const float4*)gw)[threadIdx.x];
    float o0 = v.x * s * g.x, o1 = v.y * s * g.y;
    float o2 = v.z * s * g.z, o3 = v.w * s * g.w;
    __nv_bfloat162 h01, l01, h23, l23;
    split2(o0, o1, h01, l01);
    split2(o2, o3, h23, l23);
    size_t base2 = (size_t)row * (DDIM / 2) + threadIdx.x * 2;
    ((__nv_bfloat162*)Sh)[base2]     = h01;
    ((__nv_bfloat162*)Sh)[base2 + 1] = h23;
    ((__nv_bfloat162*)Sl)[base2]     = l01;
    ((__nv_bfloat162*)Sl)[base2 + 1] = l23;
}

// ---------------- chunked RG-LRU scan --------------------------------------
// pass 1: fused gate computation + per-chunk local scan
__global__ void scan1_kernel(const float* __restrict__ rt, const float* __restrict__ it,
                             const float* __restrict__ rg, const float* __restrict__ Lam,
                             float* __restrict__ hl,
                             float* __restrict__ Acar, float* __restrict__ Hcar) {
    int i = blockIdx.x * 256 + threadIdx.x;     // 0 .. 131071
    int chain = i & (NCHAIN - 1);
    int chunk = i >> 12;
    int b = chain >> 10, d = chain & (DDIM - 1);
    size_t base = ((size_t)b * TLEN + (size_t)chunk * CHLEN) * DDIM + d;
    float la = -log1pf(expf(-Lam[d]));
    float h = 0.0f, P = 1.0f;
    for (int t = 0; t < CHLEN; t++) {
        size_t a_ = base + (size_t)t * DDIM;
        float r  = rt[a_];
        float iv = it[a_];
        float xv = rg[a_];
        float a = expf(la * sigmoidf_(r) * 0.125f);
        float g = sqrtf(fmaxf(1.0f - a * a, 0.0f)) * sigmoidf_(iv) * xv;
        h = fmaf(a, h, g);
        P *= a;
        hl[a_] = h;
    }
    Acar[i] = P;
    Hcar[i] = h;
}

// pass 2: serial scan over chunk aggregates (per chain)
__global__ void scan2_kernel(const float* __restrict__ Acar, const float* __restrict__ Hcar,
                             float* __restrict__ carry) {
    int chain = blockIdx.x * 256 + threadIdx.x;   // 0..4095
    float h = 0.0f;
    #pragma unroll
    for (int c = 0; c < CHUNKS; c++) {
        int idx = c * NCHAIN + chain;
        carry[idx] = h;
        h = fmaf(Acar[idx], h, Hcar[idx]);
    }
}

// pass 3: apply carry, fused gelu(lin)*h, write bf16 split
__global__ void scan3_kernel(const float* __restrict__ rt, const float* __restrict__ hl,
                             const float* __restrict__ carry, const float* __restrict__ lin,
                             const float* __restrict__ Lam,
                             __nv_bfloat16* __restrict__ Sh, __nv_bfloat16* __restrict__ Sl) {
    int i = blockIdx.x * 256 + threadIdx.x;
    int chain = i & (NCHAIN - 1);
    int chunk = i >> 12;
    int b = chain >> 10, d = chain & (DDIM - 1);
    size_t base = ((size_t)b * TLEN + (size_t)chunk * CHLEN) * DDIM + d;
    float la = -log1pf(expf(-Lam[d]));
    float cin = carry[i];
    float P = 1.0f;
    for (int t = 0; t < CHLEN; t++) {
        size_t a_ = base + (size_t)t * DDIM;
        float r = rt[a_];
        float a = expf(la * sigmoidf_(r) * 0.125f);
        P *= a;
        float h = fmaf(P, cin, hl[a_]);
        float l = lin[a_];
        float o = gelu_exact(l) * h;
        __nv_bfloat16 bh = __float2bfloat16_rn(o);
        __nv_bfloat16 bl = __float2bfloat16_rn(o - __bfloat162float(bh));
        Sh[a_] = bh;
        Sl[a_] = bl;
    }
}

// ---------------- gelu(sigmoid(t1)) * t2 -> bf16 split ---------------------
__global__ void comb_split_kernel(const float* __restrict__ t1,
                                  const float* __restrict__ t2,
                                  __nv_bfloat16* __restrict__ Sh,
                                  __nv_bfloat16* __restrict__ Sl) {
    int i = blockIdx.x * blockDim.x + threadIdx.x;
    if (i >= MROWS * DDIM / 4) return;
    float4 a = ((const float4*)t1)[i];
    float4 b = ((const float4*)t2)[i];
    float o0 = gelu_exact(sigmoidf_(a.x)) * b.x;
    float o1 = gelu_exact(sigmoidf_(a.y)) * b.y;
    float o2 = gelu_exact(sigmoidf_(a.z)) * b.z;
    float o3 = gelu_exact(sigmoidf_(a.w)) * b.w;
    __nv_bfloat162 h01, l01, h23, l23;
    split2(o0, o1, h01, l01);
    split2(o2, o3, h23, l23);
    ((__nv_bfloat162*)Sh)[2 * i]     = h01;
    ((__nv_bfloat162*)Sh)[2 * i + 1] = h23;
    ((__nv_bfloat162*)Sl)[2 * i]     = l01;
    ((__nv_bfloat162*)Sl)[2 * i + 1] = l23;
}

// ---------------- launch ---------------------------------------------------
extern "C" void kernel_launch(void* const* d_in, const int* in_sizes, int n_in,
                              void* d_out, int out_size) {
    const float* x      = (const float*)d_in[0];
    const float* g1     = (const float*)d_in[1];
    const float* g2     = (const float*)d_in[2];
    const float* W_lin  = (const float*)d_in[3];
    const float* b_lin  = (const float*)d_in[4];
    const float* W_conv = (const float*)d_in[5];
    const float* b_conv = (const float*)d_in[6];
    const float* W_lin2 = (const float*)d_in[7];
    const float* b_lin2 = (const float*)d_in[8];
    const float* Wa     = (const float*)d_in[9];
    const float* ba     = (const float*)d_in[10];
    const float* Wx     = (const float*)d_in[11];
    const float* bx     = (const float*)d_in[12];
    const float* Lam    = (const float*)d_in[13];
    const float* W1     = (const float*)d_in[14];
    const float* b1     = (const float*)d_in[15];
    const float* W2     = (const float*)d_in[16];
    const float* b2     = (const float*)d_in[17];
    const float* W3     = (const float*)d_in[18];
    const float* b3     = (const float*)d_in[19];
    float* out = (float*)d_out;

    float *lin, *rg, *rt, *it, *res, *hl, *Acar, *Hcar, *carry;
    __nv_bfloat16 *A0h, *A0l, *A1h, *A1l, *Wh, *Wl;
    cudaGetSymbolAddress((void**)&lin, g_lin);
    cudaGetSymbolAddress((void**)&rg,  g_rg);
    cudaGetSymbolAddress((void**)&rt,  g_rt);
    cudaGetSymbolAddress((void**)&it,  g_it);
    cudaGetSymbolAddress((void**)&res, g_res);
    cudaGetSymbolAddress((void**)&hl,  g_hl);
    cudaGetSymbolAddress((void**)&Acar, g_Acar);
    cudaGetSymbolAddress((void**)&Hcar, g_Hcar);
    cudaGetSymbolAddress((void**)&carry, g_carry);
    cudaGetSymbolAddress((void**)&A0h, g_A0h);
    cudaGetSymbolAddress((void**)&A0l, g_A0l);
    cudaGetSymbolAddress((void**)&A1h, g_A1h);
    cudaGetSymbolAddress((void**)&A1l, g_A1l);
    cudaGetSymbolAddress((void**)&Wh,  g_Wh);
    cudaGetSymbolAddress((void**)&Wl,  g_Wl);

    const int GEMM_SMEM = NSTAGE * STAGE_BYTES + 1024;   // 99328
    cudaFuncSetAttribute(mma_gemm_kernel,
                         cudaFuncAttributeMaxDynamicSharedMemorySize, GEMM_SMEM);

    dim3 gg(DDIM / 64, MROWS / 128);   // (16, 128)
    int ewBlocks  = (MROWS * DDIM / 4 + 255) / 256;
    int wBlocks   = (DDIM * DDIM / 4 + 255) / 256;
    int scBlocks  = (NCHAIN * CHUNKS) / 256;   // 512

    #define SPLIT_W(srcp) split_kernel<<<wBlocks, 256>>>(srcp, Wh, Wl, DDIM * DDIM / 4)
    #define GEMM(inH, inL, biasp, addq, outp, da, sh, sl) \
        mma_gemm_kernel<<<gg, 256, GEMM_SMEM>>>(inH, inL, Wh, Wl, biasp, addq, outp, da, sh, sl)

    // 1) A0 = split(rmsnorm(x, g1))
    rmsnorm_split_kernel<<<MROWS, 256>>>(x, g1, A0h, A0l);
    // 2) lin = xn @ W_lin^T + b_lin ; A1 = split(lin)
    SPLIT_W(W_lin); GEMM(A0h, A0l, b_lin, x, lin, 0, A1h, A1l);
    // 3) rg = lin @ W_conv^T + b_conv ; A0 = split(rg)
    SPLIT_W(W_conv); GEMM(A1h, A1l, b_conv, x, rg, 0, A0h, A0l);
    // 4) rt = rg @ Wa^T + ba ; it = rg @ Wx^T + bx
    SPLIT_W(Wa); GEMM(A0h, A0l, ba, x, rt, 0, (__nv_bfloat16*)nullptr, (__nv_bfloat16*)nullptr);
    SPLIT_W(Wx); GEMM(A0h, A0l, bx, x, it, 0, (__nv_bfloat16*)nullptr, (__nv_bfloat16*)nullptr);
    // 5-7) chunked scan with fused gateprep + fused gelu(lin)*h + split
    scan1_kernel<<<scBlocks, 256>>>(rt, it, rg, Lam, hl, Acar, Hcar);
    scan2_kernel<<<NCHAIN / 256, 256>>>(Acar, Hcar, carry);
    scan3_kernel<<<scBlocks, 256>>>(rt, hl, carry, lin, Lam, A1h, A1l);
    // 8) res = (gelu(lin)*h) @ W_lin2^T + b_lin2 + x
    SPLIT_W(W_lin2); GEMM(A1h, A1l, b_lin2, x, res, 1, (__nv_bfloat16*)nullptr, (__nv_bfloat16*)nullptr);
    // 9) A0 = split(rmsnorm(res, g2))
    rmsnorm_split_kernel<<<MROWS, 256>>>(res, g2, A0h, A0l);
    // 10) rt = xm @ W1^T + b1 ; it = xm @ W2^T + b2
    SPLIT_W(W1); GEMM(A0h, A0l, b1, x, rt, 0, (__nv_bfloat16*)nullptr, (__nv_bfloat16*)nullptr);
    SPLIT_W(W2); GEMM(A0h, A0l, b2, x, it, 0, (__nv_bfloat16*)nullptr, (__nv_bfloat16*)nullptr);
    // 11) A1 = split(gelu(sigmoid(rt)) * it)
    comb_split_kernel<<<ewBlocks, 256>>>(rt, it, A1h, A1l);
    // 12) out = combined @ W3^T + b3 + res
    SPLIT_W(W3); GEMM(A1h, A1l, b3, res, out, 1, (__nv_bfloat16*)nullptr, (__nv_bfloat16*)nullptr);

    (void)in_sizes; (void)n_in; (void)out_size;
}